// round 6
// baseline (speedup 1.0000x reference)
#include <cuda_runtime.h>
#include <cuda_bf16.h>

// Shapes: b=2, n=1024, d=128, DEPTH=4
// Outputs concatenated in d_out (fp32):
//   [0 .. 134217728)            grads  (2,1024,4,128,128)
//   [134217728 .. 134348800)    next_memories (2,4,128,128)
//   [134348800]                 losses.mean()

#define SPB 8          // samples per block in phase 1
#define TC  32         // timestep chunk in phase 2

__device__ __align__(16) float g_WT[4 * 128 * 128];          // W transposed per layer
__device__ __align__(16) float g_A [2 * 4 * 1024 * 128];     // [b][l][t][i]  layer inputs a_l
__device__ __align__(16) float g_D [2 * 4 * 1024 * 128];     // [b][l][t][j]  deltas * (-lr)
__device__ float g_lossPart[256];

// ---------------------------------------------------------------------------
// Kernel 0: WT[l][j][i] = W[l][i][j]   (coalesced writes)
// ---------------------------------------------------------------------------
__global__ void k_transpose(const float* __restrict__ W)
{
    int idx = blockIdx.x * 256 + threadIdx.x;   // 0..65535
    int l = idx >> 14;
    int j = (idx >> 7) & 127;
    int i = idx & 127;
    g_WT[idx] = W[(l << 14) + (i << 7) + j];
}

// ---------------------------------------------------------------------------
// Phase 1: per-sample forward + backward MLP -> a_l, delta_l (scaled by -lr),
// per-block loss partial sums. 128 threads, SPB samples per block.
// ---------------------------------------------------------------------------
__global__ __launch_bounds__(128) void k_phase1(
    const float* __restrict__ seq, const float* __restrict__ W,
    const float* __restrict__ Wkv, const float* __restrict__ wlr)
{
    __shared__ float Sq[SPB][128];
    __shared__ float H [SPB][128];     // current layer input (activations)
    __shared__ float Xs[3][SPB][128];  // pre-activations x0,x1,x2
    __shared__ float Dsh[SPB][128];    // current delta
    __shared__ float scale_s[SPB];     // -lr * 2/128
    __shared__ float red[SPB * 4];

    const int tid  = threadIdx.x;
    const int lane = tid & 31, wid = tid >> 5;
    const int samp0 = blockIdx.x * SPB;
    const int b  = samp0 >> 10;
    const int t0 = samp0 & 1023;

#pragma unroll
    for (int s = 0; s < SPB; s++) Sq[s][tid] = seq[(samp0 + s) * 128 + tid];
    __syncthreads();

    // adaptive_lr[s] = dot(seq_row, w_lr)
    {
        float wl = wlr[tid];
#pragma unroll
        for (int s = 0; s < SPB; s++) {
            float p = Sq[s][tid] * wl;
            p += __shfl_xor_sync(0xffffffffu, p, 16);
            p += __shfl_xor_sync(0xffffffffu, p, 8);
            p += __shfl_xor_sync(0xffffffffu, p, 4);
            p += __shfl_xor_sync(0xffffffffu, p, 2);
            p += __shfl_xor_sync(0xffffffffu, p, 1);
            if (lane == 0) red[s * 4 + wid] = p;
        }
    }
    __syncthreads();
    if (tid < SPB) {
        float lr = red[tid * 4 + 0] + red[tid * 4 + 1] + red[tid * 4 + 2] + red[tid * 4 + 3];
        scale_s[tid] = -lr * (2.0f / 128.0f);
    }

    // kv = seq_row @ Wkv ; keys -> H (and a_0 scratch), values -> regs
    float accv[SPB];
    {
        float acck[SPB];
#pragma unroll
        for (int s = 0; s < SPB; s++) { acck[s] = 0.f; accv[s] = 0.f; }
        for (int i = 0; i < 128; i++) {
            float wk = Wkv[i * 256 + tid];
            float wv = Wkv[i * 256 + 128 + tid];
#pragma unroll
            for (int s = 0; s < SPB; s++) {
                float h = Sq[s][i];
                acck[s] += h * wk;
                accv[s] += h * wv;
            }
        }
        const int Ab = ((b * 4 + 0) * 1024 + t0) * 128;
#pragma unroll
        for (int s = 0; s < SPB; s++) {
            H[s][tid] = acck[s];
            g_A[Ab + s * 128 + tid] = acck[s];
        }
    }
    __syncthreads();

    // forward
    float pred[SPB];
    for (int l = 0; l < 4; l++) {
        float acc[SPB];
#pragma unroll
        for (int s = 0; s < SPB; s++) acc[s] = 0.f;
        const float* Wl = W + (l << 14);
        for (int i = 0; i < 128; i++) {
            float w = Wl[(i << 7) + tid];
#pragma unroll
            for (int s = 0; s < SPB; s++) acc[s] += H[s][i] * w;
        }
        __syncthreads();
        if (l < 3) {
            const int Ab = ((b * 4 + (l + 1)) * 1024 + t0) * 128;
#pragma unroll
            for (int s = 0; s < SPB; s++) {
                float x  = acc[s];
                Xs[l][s][tid] = x;
                float sg = 1.0f / (1.0f + __expf(-x));
                float h  = x * sg;
                H[s][tid] = h;
                g_A[Ab + s * 128 + tid] = h;
            }
            __syncthreads();
        } else {
#pragma unroll
            for (int s = 0; s < SPB; s++) pred[s] = acc[s];
        }
    }

    // loss + delta3 (scaled by -lr * 2/d)
    float diff[SPB];
#pragma unroll
    for (int s = 0; s < SPB; s++) diff[s] = pred[s] - accv[s];
#pragma unroll
    for (int s = 0; s < SPB; s++) {
        float p = diff[s] * diff[s];
        p += __shfl_xor_sync(0xffffffffu, p, 16);
        p += __shfl_xor_sync(0xffffffffu, p, 8);
        p += __shfl_xor_sync(0xffffffffu, p, 4);
        p += __shfl_xor_sync(0xffffffffu, p, 2);
        p += __shfl_xor_sync(0xffffffffu, p, 1);
        if (lane == 0) red[s * 4 + wid] = p;
    }
    __syncthreads();
    if (tid == 0) {
        float tot = 0.f;
        for (int k2 = 0; k2 < SPB * 4; k2++) tot += red[k2];
        g_lossPart[blockIdx.x] = tot * (1.0f / 128.0f);
    }
    {
        const int Db = ((b * 4 + 3) * 1024 + t0) * 128;
#pragma unroll
        for (int s = 0; s < SPB; s++) {
            float dl = scale_s[s] * diff[s];
            Dsh[s][tid] = dl;
            g_D[Db + s * 128 + tid] = dl;
        }
    }
    __syncthreads();

    // backward: e = W^T delta (via WT, coalesced), delta_{l-1} = e * silu'(x_{l-1})
    for (int l = 3; l >= 1; l--) {
        float acc[SPB];
#pragma unroll
        for (int s = 0; s < SPB; s++) acc[s] = 0.f;
        const float* WTl = g_WT + (l << 14);
        for (int j = 0; j < 128; j++) {
            float w = WTl[(j << 7) + tid];
#pragma unroll
            for (int s = 0; s < SPB; s++) acc[s] += Dsh[s][j] * w;
        }
        __syncthreads();
        const int Db = ((b * 4 + (l - 1)) * 1024 + t0) * 128;
#pragma unroll
        for (int s = 0; s < SPB; s++) {
            float x    = Xs[l - 1][s][tid];
            float sg   = 1.0f / (1.0f + __expf(-x));
            float dsil = sg * (1.0f + x * (1.0f - sg));
            float dl   = acc[s] * dsil;
            Dsh[s][tid] = dl;
            g_D[Db + s * 128 + tid] = dl;
        }
        __syncthreads();
    }
}

// ---------------------------------------------------------------------------
// Phase 2: inclusive scan over t of rank-1 outer products, streamed to d_out.
// grid = 8 (b,l) * 32 tiles = 256 blocks (all co-resident), 128 threads.
// Block covers 4 rows (i) x 128 cols (j), thread owns a float4 of j.
// Also writes next_memories and the loss scalar.
// ---------------------------------------------------------------------------
__global__ __launch_bounds__(128) void k_phase2(const float* __restrict__ W,
                                                float* __restrict__ out)
{
    __shared__ float dCh[TC * 128];
    __shared__ float aCh[4][TC + 1];

    const int tid  = threadIdx.x;
    const int bl   = blockIdx.x >> 5;      // 0..7  (b*4 + l)
    const int tile = blockIdx.x & 31;      // i tile
    const int b = bl >> 2, l = bl & 3;
    const int iLocal = tid >> 5, jq = tid & 31;
    const int i = tile * 4 + iLocal;

    // deterministic loss reduction (phase-1 partials are complete: prior kernel)
    if (blockIdx.x == 0 && tid < 32) {
        float s2 = 0.f;
        for (int k2 = tid; k2 < 256; k2 += 32) s2 += g_lossPart[k2];
        s2 += __shfl_xor_sync(0xffffffffu, s2, 16);
        s2 += __shfl_xor_sync(0xffffffffu, s2, 8);
        s2 += __shfl_xor_sync(0xffffffffu, s2, 4);
        s2 += __shfl_xor_sync(0xffffffffu, s2, 2);
        s2 += __shfl_xor_sync(0xffffffffu, s2, 1);
        if (tid == 0) out[134348800] = s2 * (1.0f / 2048.0f);
    }

    const float* Abl = g_A + bl * (1024 * 128);
    const float* Dbl = g_D + bl * (1024 * 128);
    float4 acc = make_float4(0.f, 0.f, 0.f, 0.f);

    for (int c = 0; c < 1024 / TC; c++) {
        // stage TC timesteps of delta (coalesced float4) + a values for our 4 rows
        const float4* dsrc = (const float4*)(Dbl + c * TC * 128);
        float4* ddst = (float4*)dCh;
#pragma unroll
        for (int k2 = 0; k2 < 8; k2++) ddst[tid + k2 * 128] = dsrc[tid + k2 * 128];
        {
            int tt = tid >> 2, il = tid & 3;
            aCh[il][tt] = Abl[(c * TC + tt) * 128 + tile * 4 + il];
        }
        __syncthreads();

#pragma unroll
        for (int tt = 0; tt < TC; tt++) {
            float  a  = aCh[iLocal][tt];                         // broadcast
            float4 dv = ((const float4*)dCh)[tt * 32 + jq];      // conflict-free
            acc.x += a * dv.x; acc.y += a * dv.y;
            acc.z += a * dv.z; acc.w += a * dv.w;
            int t = c * TC + tt;
            long oidx = ((long)(((b << 10) + t) * 4 + l) << 14) + (i << 7) + (jq << 2);
            *(float4*)(out + oidx) = acc;                        // STG.128 coalesced
        }
        __syncthreads();
    }

    // next_memories = W + grads[:, -1]
    {
        const float* Wl = W + (l << 14);
        float4 wv = *(const float4*)(Wl + (i << 7) + (jq << 2));
        float4 nm = make_float4(acc.x + wv.x, acc.y + wv.y, acc.z + wv.z, acc.w + wv.w);
        long nmIdx = 134217728L + ((long)(b * 4 + l) << 14) + (i << 7) + (jq << 2);
        *(float4*)(out + nmIdx) = nm;
    }
}

// ---------------------------------------------------------------------------
extern "C" void kernel_launch(void* const* d_in, const int* in_sizes, int n_in,
                              void* d_out, int out_size)
{
    (void)in_sizes; (void)n_in; (void)out_size;
    const float* seq = (const float*)d_in[0];
    const float* W   = (const float*)d_in[1];
    const float* Wkv = (const float*)d_in[2];
    const float* wlr = (const float*)d_in[3];
    // d_in[4] (w_mom), d_in[5] (w_decay) do not affect the outputs.
    float* out = (float*)d_out;

    k_transpose<<<256, 256>>>(W);
    k_phase1<<<256, 128>>>(seq, W, Wkv, wlr);
    k_phase2<<<256, 128>>>(W, out);
}